// round 13
// baseline (speedup 1.0000x reference)
#include <cuda_runtime.h>
#include <math.h>

#define BB   8
#define FF   48
#define SS   64
#define DD   512
#define NHH  8
#define DHH  64
#define LLAY 4
#define DFFF 2048
#define MMM  64
#define LNEPS 1e-5f
#define GRID 128          // 8 groups x 16 blocks; all co-resident
#define GPB  16           // blocks per group (one batch per group)

// ---------------- scratch (device globals; allocation-free) ----------------
__device__ __align__(16) float g_q   [BB*DD];
__device__ __align__(16) float g_xb  [BB*DD];
__device__ __align__(16) float g_y   [BB*DD];
__device__ __align__(16) float g_r   [BB*DD];
__device__ __align__(16) float g_hh  [BB*DFFF];
__device__ __align__(16) float g_K   [LLAY*BB*FF*DD];
__device__ __align__(16) float g_V   [LLAY*BB*FF*DD];
__device__ __align__(16) float g_XA  [LLAY*BB*FF*DD];
__device__ __align__(16) float g_E2  [BB*FF*DD];
__device__ __align__(16) float g_CW  [DD*MMM];
__device__ __align__(16) float g_cb  [DD];
__device__ __align__(16) float g_qh  [BB*FF*DD];
__device__ __align__(16) float g_kh  [BB*SS*DD];
__device__ __align__(16) float g_vh  [BB*SS*DD];
__device__ __align__(16) float g_tmpL[LLAY*BB*FF*DD];

// per-group barrier state: each group's counter/gen on its own 128B line
__device__ __align__(128) unsigned g_bcnt[8*32];
__device__ __align__(128) unsigned g_bgen[8*32];

// ---------------- helpers ----------------
__device__ __forceinline__ float warp_sum(float v){
#pragma unroll
    for (int o = 16; o; o >>= 1) v += __shfl_xor_sync(0xffffffffu, v, o);
    return v;
}
__device__ __forceinline__ float dot4(float4 a, float4 b){
    return a.x*b.x + a.y*b.y + a.z*b.z + a.w*b.w;
}
__device__ __forceinline__ float4 ld_cg4(const float* p){
    float4 v;
    asm volatile("ld.global.cg.v4.f32 {%0,%1,%2,%3}, [%4];"
                 : "=f"(v.x), "=f"(v.y), "=f"(v.z), "=f"(v.w) : "l"(p));
    return v;
}
__device__ __forceinline__ void st_cg(float* p, float v){
    asm volatile("st.global.cg.f32 [%0], %1;" :: "l"(p), "f"(v) : "memory");
}

// per-group barrier: monotonic counter, release-arrive, relaxed poll
__device__ __forceinline__ void group_sync(unsigned &phase, int g){
    __syncthreads();
    if (threadIdx.x == 0){
        unsigned prev;
        asm volatile("atom.add.acq_rel.gpu.u32 %0, [%1], 1;"
                     : "=r"(prev) : "l"(&g_bcnt[g*32]) : "memory");
        if (prev == phase*16u + 15u){
            asm volatile("st.release.gpu.u32 [%0], %1;"
                         :: "l"(&g_bgen[g*32]), "r"(phase + 1u) : "memory");
        }
        unsigned cur;
        do {
            asm volatile("ld.relaxed.gpu.u32 %0, [%1];" : "=r"(cur) : "l"(&g_bgen[g*32]) : "memory");
        } while (cur <= phase);
    }
    phase++;
    __syncthreads();
}

__global__ void reset_barrier_kernel(){
    int t = threadIdx.x;
    if (t < 8){ g_bcnt[t*32] = 0; g_bgen[t*32] = 0; }
}

// ================= one-time precompute kernels =================

__global__ void gemm_rows_kernel(float* __restrict__ out, const float* __restrict__ X,
                                 const float* __restrict__ W, const float* __restrict__ bias,
                                 int N, int K){
    int warp = threadIdx.x >> 5, lane = threadIdx.x & 31;
    int n  = blockIdx.x * 8 + warp;
    int r0 = blockIdx.y * 8;
    const float4* w4 = (const float4*)(W + (size_t)n * K);
    const float* x = X + (size_t)r0 * K;
    int K4 = K >> 2;
    float acc[8] = {0.f,0.f,0.f,0.f,0.f,0.f,0.f,0.f};
    for (int i = lane; i < K4; i += 32){
        float4 wv = w4[i];
#pragma unroll
        for (int b = 0; b < 8; b++)
            acc[b] += dot4(wv, ((const float4*)(x + (size_t)b*K))[i]);
    }
#pragma unroll
    for (int o = 16; o; o >>= 1){
#pragma unroll
        for (int b = 0; b < 8; b++) acc[b] += __shfl_xor_sync(0xffffffffu, acc[b], o);
    }
    float bv = bias[n];
#pragma unroll
    for (int b = 0; b < 8; b++)
        if (lane == b) out[(size_t)(r0 + b) * N + n] = acc[b] + bv;
}

__global__ void gemm_rows_z_kernel(float* __restrict__ out0, const float* __restrict__ X0,
                                   const float* __restrict__ W0, const float* __restrict__ b0,
                                   int N, int K, int R,
                                   size_t outSZ, size_t xSZ, size_t wSZ, size_t bSZ){
    int z = blockIdx.z;
    float* out = out0 + (size_t)z*outSZ;
    const float* X = X0 + (size_t)z*xSZ;
    const float* W = W0 + (size_t)z*wSZ;
    const float* bias = b0 + (size_t)z*bSZ;
    int warp = threadIdx.x >> 5, lane = threadIdx.x & 31;
    int n  = blockIdx.x * 8 + warp;
    int r0 = blockIdx.y * 8;
    if (r0 >= R) return;
    const float4* w4 = (const float4*)(W + (size_t)n * K);
    const float* x = X + (size_t)r0 * K;
    int K4 = K >> 2;
    float acc[8] = {0.f,0.f,0.f,0.f,0.f,0.f,0.f,0.f};
    for (int i = lane; i < K4; i += 32){
        float4 wv = w4[i];
#pragma unroll
        for (int b = 0; b < 8; b++)
            acc[b] += dot4(wv, ((const float4*)(x + (size_t)b*K))[i]);
    }
#pragma unroll
    for (int o = 16; o; o >>= 1){
#pragma unroll
        for (int b = 0; b < 8; b++) acc[b] += __shfl_xor_sync(0xffffffffu, acc[b], o);
    }
    float bv = bias[n];
#pragma unroll
    for (int b = 0; b < 8; b++)
        if (lane == b) out[(size_t)(r0 + b) * N + n] = acc[b] + bv;
}

__global__ void ca_inproj_kernel(const float* __restrict__ content, const float* __restrict__ style,
                                 const float* __restrict__ ca_in_w, const float* __restrict__ ca_in_b,
                                 float* __restrict__ qh, float* __restrict__ kh, float* __restrict__ vh){
    int z = blockIdx.z;
    const float* X = (z == 0) ? content : style;
    int R = (z == 0) ? BB*FF : BB*SS;
    float* out = (z == 0) ? qh : (z == 1 ? kh : vh);
    const float* W = ca_in_w + (size_t)z*DD*DD;
    const float* bias = ca_in_b + z*DD;
    int warp = threadIdx.x >> 5, lane = threadIdx.x & 31;
    int n  = blockIdx.x * 8 + warp;
    int r0 = blockIdx.y * 8;
    if (r0 >= R) return;
    const float4* w4 = (const float4*)(W + (size_t)n * DD);
    const float* x = X + (size_t)r0 * DD;
    float acc[8] = {0.f,0.f,0.f,0.f,0.f,0.f,0.f,0.f};
#pragma unroll
    for (int q = 0; q < 4; q++){
        int i = lane + q*32;
        float4 wv = w4[i];
#pragma unroll
        for (int b = 0; b < 8; b++)
            acc[b] += dot4(wv, ((const float4*)(x + (size_t)b*DD))[i]);
    }
#pragma unroll
    for (int o = 16; o; o >>= 1){
#pragma unroll
        for (int b = 0; b < 8; b++) acc[b] += __shfl_xor_sync(0xffffffffu, acc[b], o);
    }
    float bv = bias[n];
#pragma unroll
    for (int b = 0; b < 8; b++)
        if (lane == b) out[(size_t)(r0 + b) * DD + n] = acc[b] + bv;
}

__global__ void ca_attn_kernel(const float* __restrict__ qh, const float* __restrict__ kh,
                               const float* __restrict__ vh, float* __restrict__ o){
    int r = blockIdx.x;
    int b = r / FF;
    __shared__ __align__(16) float s_q[DD];
    __shared__ float s_p[SS];
    int tid = threadIdx.x, warp = tid >> 5, lane = tid & 31;
    for (int d = tid; d < DD; d += 256) s_q[d] = qh[(size_t)r*DD + d];
    __syncthreads();
    for (int s = warp; s < SS; s += 8){
        const float4* kr4 = (const float4*)(kh + (size_t)(b*SS + s)*DD);
        float a = 0.f;
#pragma unroll
        for (int q = 0; q < 4; q++){
            int i = lane + q*32;
            a += dot4(((const float4*)s_q)[i], kr4[i]);
        }
        a = warp_sum(a);
        if (lane == 0) s_p[s] = a * 0.04419417382415922f;
    }
    __syncthreads();
    if (warp == 0){
        float v0 = s_p[lane], v1 = s_p[lane + 32];
        float m = fmaxf(v0, v1);
#pragma unroll
        for (int o2 = 16; o2; o2 >>= 1) m = fmaxf(m, __shfl_xor_sync(0xffffffffu, m, o2));
        float e0 = expf(v0 - m), e1 = expf(v1 - m);
        float sm = warp_sum(e0 + e1);
        float inv = 1.f / sm;
        s_p[lane] = e0 * inv; s_p[lane + 32] = e1 * inv;
    }
    __syncthreads();
    for (int d = tid; d < DD; d += 256){
        float a = 0.f;
#pragma unroll 8
        for (int s = 0; s < SS; s++) a += s_p[s] * vh[(size_t)(b*SS + s)*DD + d];
        o[(size_t)r*DD + d] = a;
    }
}

__global__ void e2_kernel(const float* __restrict__ sel, const float* __restrict__ se_w,
                          const float* __restrict__ se_b, const float* __restrict__ style){
    int warp = threadIdx.x >> 5, lane = threadIdx.x & 31;
    int n  = blockIdx.x * 8 + warp;
    int r0 = blockIdx.y * 8;
    int b  = r0 / FF;
    const float4* w4 = (const float4*)(se_w + (size_t)n * 1024 + 512);
    const float4* xr[8];
#pragma unroll
    for (int q = 0; q < 8; q++){
        int p  = (r0 + q) % FF;
        int ip = p ? (p - 1) : 0;
        xr[q] = (const float4*)(sel + ((size_t)b*FF + ip)*DD);
    }
    float acc[8] = {0.f,0.f,0.f,0.f,0.f,0.f,0.f,0.f};
#pragma unroll
    for (int i4 = 0; i4 < 4; i4++){
        int i = lane + i4*32;
        float4 wv = w4[i];
#pragma unroll
        for (int q = 0; q < 8; q++) acc[q] += dot4(wv, xr[q][i]);
    }
#pragma unroll
    for (int o = 16; o; o >>= 1){
#pragma unroll
        for (int q = 0; q < 8; q++) acc[q] += __shfl_xor_sync(0xffffffffu, acc[q], o);
    }
#pragma unroll
    for (int q = 0; q < 8; q++){
        if (lane == q){
            int p = (r0 + q) % FF;
            float pos = (float)(p % 30);
            const float LF = 9.210340371976184f / 512.f;
            float pe;
            if (n & 1) pe = cosf(pos * expf(-(float)(n - 1) * LF));
            else       pe = sinf(pos * expf(-(float)n       * LF));
            g_E2[((size_t)r0 + q)*DD + n] = acc[q] + se_b[n] + style[b*DD + n] + pe;
        }
    }
}

__global__ void cw_kernel(const float* __restrict__ se_w, const float* __restrict__ mm_w,
                          const float* __restrict__ mm_b){
    int d = blockIdx.x, j = threadIdx.x;
    __shared__ float s_w1[DD];
    for (int k = j; k < DD; k += 64) s_w1[k] = se_w[(size_t)d*1024 + k];
    __syncthreads();
    float a = 0.f;
    for (int k = 0; k < DD; k++) a += s_w1[k] * mm_w[(size_t)k*MMM + j];
    g_CW[(size_t)d*MMM + j] = a;
    if (j == 0){
        float c = 0.f;
        for (int k = 0; k < DD; k++) c += s_w1[k] * mm_b[k];
        g_cb[d] = c;
    }
}

__global__ void init_x0_kernel(const float* __restrict__ init_state, const float* __restrict__ mm_w,
                               const float* __restrict__ mm_b, const float* __restrict__ se_w){
    int b = blockIdx.x, d = threadIdx.x;
    __shared__ __align__(16) float s_feat[DD];
    float a = mm_b[d];
    const float* mw = mm_w + (size_t)d * MMM;
    const float* is = init_state + b * MMM;
#pragma unroll
    for (int k = 0; k < MMM; k++) a += is[k] * mw[k];
    s_feat[d] = a;
    __syncthreads();
    const float4* w14 = (const float4*)(se_w + (size_t)d * 1024);
    float acc = 0.f;
#pragma unroll
    for (int i = 0; i < 128; i++) acc += dot4(((const float4*)s_feat)[i], w14[i]);
    g_xb[b*DD + d] = acc + g_E2[((size_t)b*FF + 0)*DD + d];
}

// ================= persistent decode kernel (8 independent batch groups) ========
__global__ void __launch_bounds__(256, 1) decode_kernel(
    const float* __restrict__ sa_in_w,  const float* __restrict__ sa_in_b,
    const float* __restrict__ sa_out_w, const float* __restrict__ sa_out_b,
    const float* __restrict__ ff1_w,    const float* __restrict__ ff1_b,
    const float* __restrict__ ff2_w,    const float* __restrict__ ff2_b,
    const float* __restrict__ ln_g,     const float* __restrict__ ln_b,
    const float* __restrict__ mmr_w,    const float* __restrict__ mmr_b,
    float* __restrict__ dec_out)
{
    int tid = threadIdx.x, w = tid >> 5, lane = tid & 31;
    int g   = blockIdx.x >> 4;         // batch / barrier group
    int sub = blockIdx.x & 15;         // block within group
    int gw16 = sub*8 + w;              // warp index within group (0..127)
    unsigned phase = 0;

    __shared__ __align__(16) float s_x  [DD];    // layer input (this batch)
    __shared__ __align__(16) float s_x2 [DD];    // post-LN2 (this batch)
    __shared__ __align__(16) float s_attn[DD];
    __shared__ __align__(16) float s_qb [8][DHH];
    __shared__ __align__(16) float s_h  [DFFF];  // ff1 activations staged
    __shared__ float s_p [8][FF];
    __shared__ float s_out[MMM];

    for (int t = 0; t < FF; t++){
        for (int l = 0; l < LLAY; l++){
            // ==== Stage A: layer input (LN3 fused for l>0) + qkv slice ====
            if (l == 0){
                if (tid < 128) ((float4*)s_x)[tid] = ld_cg4(g_xb + g*DD + tid*4);
            } else {
                const float4* lng = (const float4*)(ln_g + ((size_t)(l-1)*3 + 2)*DD);
                const float4* lnb = (const float4*)(ln_b + ((size_t)(l-1)*3 + 2)*DD);
                float4 v[4]; float s = 0.f;
#pragma unroll
                for (int q = 0; q < 4; q++){
                    int i = lane + q*32;
                    float4 a = ((const float4*)s_x2)[i];
                    float4 y = ld_cg4(g_y + g*DD + i*4);
                    v[q].x = a.x+y.x; v[q].y = a.y+y.y; v[q].z = a.z+y.z; v[q].w = a.w+y.w;
                    s += v[q].x+v[q].y+v[q].z+v[q].w;
                }
                s = warp_sum(s); float mu = s * (1.f/DD);
                float vs = 0.f;
#pragma unroll
                for (int q = 0; q < 4; q++){
                    float dx=v[q].x-mu, dy=v[q].y-mu, dz=v[q].z-mu, dw=v[q].w-mu;
                    vs += dx*dx+dy*dy+dz*dz+dw*dw;
                }
                vs = warp_sum(vs); float rstd = rsqrtf(vs*(1.f/DD) + LNEPS);
                if (w < 4){
                    int i = lane + w*32;
                    float4 gg = lng[i], bb = lnb[i], o;
                    o.x = (v[w].x-mu)*rstd*gg.x + bb.x;
                    o.y = (v[w].y-mu)*rstd*gg.y + bb.y;
                    o.z = (v[w].z-mu)*rstd*gg.z + bb.z;
                    o.w = (v[w].w-mu)*rstd*gg.w + bb.w;
                    ((float4*)s_x)[i] = o;
                }
            }
            __syncthreads();
            {
                const float* Wq = sa_in_w + (size_t)l*3*DD*DD;
                const float* bq = sa_in_b + (size_t)l*3*DD;
#pragma unroll
                for (int c = 0; c < 3; c++){
                    float acc[4] = {0.f,0.f,0.f,0.f};
                    int r0 = gw16 + c*512;
#pragma unroll
                    for (int rr = 0; rr < 4; rr++){
                        const float4* w4 = (const float4*)(Wq + (size_t)(r0 + rr*128)*DD);
#pragma unroll
                        for (int q = 0; q < 4; q++){
                            int i = lane + q*32;
                            acc[rr] += dot4(w4[i], ((const float4*)s_x)[i]);
                        }
                    }
#pragma unroll
                    for (int o = 16; o; o >>= 1){
#pragma unroll
                        for (int rr = 0; rr < 4; rr++) acc[rr] += __shfl_xor_sync(0xffffffffu, acc[rr], o);
                    }
#pragma unroll
                    for (int rr = 0; rr < 4; rr++){
                        if (lane == rr){
                            int n = r0 + rr*128;
                            float val = acc[rr] + bq[n];
                            if (n < DD)        st_cg(g_q + g*DD + n, val);
                            else if (n < 2*DD) st_cg(g_K + (((size_t)l*BB + g)*FF + t)*DD + (n - DD), val);
                            else               st_cg(g_V + (((size_t)l*BB + g)*FF + t)*DD + (n - 2*DD), val);
                        }
                    }
                }
            }
            group_sync(phase, g);

            // ==== Stage B: attention (8 warps = 8 heads, redundant per block) + out-proj ====
            {
                int h = w;
                if (lane < 16) ((float4*)s_qb[w])[lane] = ld_cg4(g_q + g*DD + h*DHH + lane*4);
                __syncwarp();
                const float* Kb = g_K + (((size_t)l*BB + g)*FF)*DD + h*DHH;
                const float* Vb = g_V + (((size_t)l*BB + g)*FF)*DD + h*DHH;
                float slope = exp2f(-(float)(h + 1));
                int j0 = lane, j1 = lane + 32;
                float sc0 = -1e30f, sc1 = -1e30f;
                if (j0 <= t){
                    const float4* kr = (const float4*)(Kb + (size_t)j0*DD);
                    float a = 0.f;
#pragma unroll
                    for (int i = 0; i < 16; i++) a += dot4(((const float4*)s_qb[w])[i], kr[i]);
                    sc0 = a*0.125f - slope * (float)((t - j0)/30);
                }
                if (j1 <= t){
                    const float4* kr = (const float4*)(Kb + (size_t)j1*DD);
                    float a = 0.f;
#pragma unroll
                    for (int i = 0; i < 16; i++) a += dot4(((const float4*)s_qb[w])[i], kr[i]);
                    sc1 = a*0.125f - slope * (float)((t - j1)/30);
                }
                float m = fmaxf(sc0, sc1);
#pragma unroll
                for (int o = 16; o; o >>= 1) m = fmaxf(m, __shfl_xor_sync(0xffffffffu, m, o));
                float e0 = (j0 <= t) ? expf(sc0 - m) : 0.f;
                float e1 = (j1 <= t) ? expf(sc1 - m) : 0.f;
                float sm = warp_sum(e0 + e1);
                float inv = 1.f / sm;
                s_p[w][j0] = e0 * inv;
                if (j1 < FF) s_p[w][j1] = e1 * inv;
                __syncwarp();
#pragma unroll
                for (int dq = 0; dq < 2; dq++){
                    int d = lane + dq*32;
                    float a = 0.f;
#pragma unroll 4
                    for (int j = 0; j <= t; j++) a += s_p[w][j] * Vb[(size_t)j*DD + d];
                    s_attn[h*DHH + d] = a;
                }
            }
            __syncthreads();
            {
                const float* Wo = sa_out_w + (size_t)l*DD*DD;
                const float* bo = sa_out_b + (size_t)l*DD;
                float acc[4] = {0.f,0.f,0.f,0.f};
                int d0 = sub*32 + w*4;
#pragma unroll
                for (int u = 0; u < 4; u++){
                    const float4* w4 = (const float4*)(Wo + (size_t)(d0 + u)*DD);
#pragma unroll
                    for (int q = 0; q < 4; q++){
                        int i = lane + q*32;
                        acc[u] += dot4(w4[i], ((const float4*)s_attn)[i]);
                    }
                }
#pragma unroll
                for (int o = 16; o; o >>= 1){
#pragma unroll
                    for (int u = 0; u < 4; u++) acc[u] += __shfl_xor_sync(0xffffffffu, acc[u], o);
                }
#pragma unroll
                for (int u = 0; u < 4; u++){
                    if (lane == u){
                        int d = d0 + u;
                        st_cg(g_r + g*DD + d, acc[u] + bo[d] + s_x[d]);
                    }
                }
            }
            group_sync(phase, g);

            // ==== Stage C: LN1 + XA + LN2 (warp-redundant) then ff1 slice ====
            {
                const float4* lng1 = (const float4*)(ln_g + ((size_t)l*3 + 0)*DD);
                const float4* lnb1 = (const float4*)(ln_b + ((size_t)l*3 + 0)*DD);
                const float4* lng2 = (const float4*)(ln_g + ((size_t)l*3 + 1)*DD);
                const float4* lnb2 = (const float4*)(ln_b + ((size_t)l*3 + 1)*DD);
                const float4* xa4  = (const float4*)(g_XA + (((size_t)l*BB + g)*FF + t)*DD);
                float4 v[4]; float s = 0.f;
#pragma unroll
                for (int q = 0; q < 4; q++){
                    int i = lane + q*32;
                    v[q] = ld_cg4(g_r + g*DD + i*4);
                    s += v[q].x+v[q].y+v[q].z+v[q].w;
                }
                s = warp_sum(s); float mu = s * (1.f/DD);
                float vs = 0.f;
#pragma unroll
                for (int q = 0; q < 4; q++){
                    float dx=v[q].x-mu, dy=v[q].y-mu, dz=v[q].z-mu, dw=v[q].w-mu;
                    vs += dx*dx+dy*dy+dz*dz+dw*dw;
                }
                vs = warp_sum(vs); float rstd = rsqrtf(vs*(1.f/DD) + LNEPS);
                float s2 = 0.f;
#pragma unroll
                for (int q = 0; q < 4; q++){
                    int i = lane + q*32;
                    float4 gg = lng1[i], bb = lnb1[i], xa = xa4[i], r2;
                    r2.x = (v[q].x-mu)*rstd*gg.x + bb.x + xa.x;
                    r2.y = (v[q].y-mu)*rstd*gg.y + bb.y + xa.y;
                    r2.z = (v[q].z-mu)*rstd*gg.z + bb.z + xa.z;
                    r2.w = (v[q].w-mu)*rstd*gg.w + bb.w + xa.w;
                    v[q] = r2; s2 += r2.x+r2.y+r2.z+r2.w;
                }
                s2 = warp_sum(s2); mu = s2 * (1.f/DD);
                vs = 0.f;
#pragma unroll
                for (int q = 0; q < 4; q++){
                    float dx=v[q].x-mu, dy=v[q].y-mu, dz=v[q].z-mu, dw=v[q].w-mu;
                    vs += dx*dx+dy*dy+dz*dz+dw*dw;
                }
                vs = warp_sum(vs); rstd = rsqrtf(vs*(1.f/DD) + LNEPS);
                if (w < 4){
                    int i = lane + w*32;
                    float4 gg = lng2[i], bb = lnb2[i], o;
                    o.x = (v[w].x-mu)*rstd*gg.x + bb.x;
                    o.y = (v[w].y-mu)*rstd*gg.y + bb.y;
                    o.z = (v[w].z-mu)*rstd*gg.z + bb.z;
                    o.w = (v[w].w-mu)*rstd*gg.w + bb.w;
                    ((float4*)s_x2)[i] = o;
                }
            }
            __syncthreads();
            {
                const float* W1 = ff1_w + (size_t)l*DFFF*DD;
                const float* b1 = ff1_b + (size_t)l*DFFF;
#pragma unroll
                for (int c = 0; c < 4; c++){
                    float acc[4] = {0.f,0.f,0.f,0.f};
                    int r0 = gw16 + c*512;
#pragma unroll
                    for (int rr = 0; rr < 4; rr++){
                        const float4* w4 = (const float4*)(W1 + (size_t)(r0 + rr*128)*DD);
#pragma unroll
                        for (int q = 0; q < 4; q++){
                            int i = lane + q*32;
                            acc[rr] += dot4(w4[i], ((const float4*)s_x2)[i]);
                        }
                    }
#pragma unroll
                    for (int o = 16; o; o >>= 1){
#pragma unroll
                        for (int rr = 0; rr < 4; rr++) acc[rr] += __shfl_xor_sync(0xffffffffu, acc[rr], o);
                    }
#pragma unroll
                    for (int rr = 0; rr < 4; rr++){
                        if (lane == rr){
                            int n = r0 + rr*128;
                            st_cg(g_hh + g*DFFF + n, fmaxf(acc[rr] + b1[n], 0.f));
                        }
                    }
                }
            }
            group_sync(phase, g);

            // ==== Stage D: ff2 (h staged into shared, 4 rows/warp) ====
            {
#pragma unroll
                for (int i = tid; i < DFFF/4; i += 256)
                    ((float4*)s_h)[i] = ld_cg4(g_hh + g*DFFF + i*4);
                __syncthreads();
                const float* W2 = ff2_w + (size_t)l*DD*DFFF;
                float acc[4] = {0.f,0.f,0.f,0.f};
                int d0 = sub*32 + w*4;
#pragma unroll
                for (int u = 0; u < 4; u++){
                    const float4* w4 = (const float4*)(W2 + (size_t)(d0 + u)*DFFF);
#pragma unroll
                    for (int q = 0; q < 16; q++){
                        int i = lane + q*32;
                        acc[u] += dot4(w4[i], ((const float4*)s_h)[i]);
                    }
                }
#pragma unroll
                for (int o = 16; o; o >>= 1){
#pragma unroll
                    for (int u = 0; u < 4; u++) acc[u] += __shfl_xor_sync(0xffffffffu, acc[u], o);
                }
#pragma unroll
                for (int u = 0; u < 4; u++){
                    if (lane == u){
                        int d = d0 + u;
                        st_cg(g_y + g*DD + d, acc[u] + ff2_b[(size_t)l*DD + d]);
                    }
                }
            }
            group_sync(phase, g);
        } // layers

        // ==== Stage H: LN3 + head (warp-redundant LN) + next embedding ====
        {
            const float4* lng3 = (const float4*)(ln_g + (size_t)((LLAY-1)*3 + 2)*DD);
            const float4* lnb3 = (const float4*)(ln_b + (size_t)((LLAY-1)*3 + 2)*DD);
            float4 x3[4]; float s = 0.f;
#pragma unroll
            for (int q = 0; q < 4; q++){
                int i = lane + q*32;
                float4 a = ((const float4*)s_x2)[i];
                float4 y = ld_cg4(g_y + g*DD + i*4);
                x3[q].x = a.x+y.x; x3[q].y = a.y+y.y; x3[q].z = a.z+y.z; x3[q].w = a.w+y.w;
                s += x3[q].x+x3[q].y+x3[q].z+x3[q].w;
            }
            s = warp_sum(s); float mu = s * (1.f/DD);
            float vs = 0.f;
#pragma unroll
            for (int q = 0; q < 4; q++){
                float dx=x3[q].x-mu, dy=x3[q].y-mu, dz=x3[q].z-mu, dw=x3[q].w-mu;
                vs += dx*dx+dy*dy+dz*dz+dw*dw;
            }
            vs = warp_sum(vs); float rstd = rsqrtf(vs*(1.f/DD) + LNEPS);
#pragma unroll
            for (int q = 0; q < 4; q++){
                int i = lane + q*32;
                float4 gg = lng3[i], bb = lnb3[i];
                x3[q].x = (x3[q].x-mu)*rstd*gg.x + bb.x;
                x3[q].y = (x3[q].y-mu)*rstd*gg.y + bb.y;
                x3[q].z = (x3[q].z-mu)*rstd*gg.z + bb.z;
                x3[q].w = (x3[q].w-mu)*rstd*gg.w + bb.w;
            }
            float acc[8] = {0.f,0.f,0.f,0.f,0.f,0.f,0.f,0.f};
#pragma unroll
            for (int jj = 0; jj < 8; jj++){
                const float4* w4 = (const float4*)(mmr_w + (size_t)(w*8 + jj)*DD);
#pragma unroll
                for (int q = 0; q < 4; q++) acc[jj] += dot4(x3[q], w4[lane + q*32]);
            }
#pragma unroll
            for (int o = 16; o; o >>= 1){
#pragma unroll
                for (int jj = 0; jj < 8; jj++) acc[jj] += __shfl_xor_sync(0xffffffffu, acc[jj], o);
            }
#pragma unroll
            for (int jj = 0; jj < 8; jj++){
                if (lane == jj){
                    int j = w*8 + jj;
                    float val = acc[jj] + mmr_b[j];
                    s_out[j] = val;
                    if (sub == 0) dec_out[((size_t)g*FF + t)*MMM + j] = val;
                }
            }
        }
        __syncthreads();
        if (t < FF - 1){
            float o0 = s_out[lane], o1 = s_out[lane + 32];
            float acc[4] = {0.f,0.f,0.f,0.f};
            int d0 = sub*32 + w*4;
#pragma unroll
            for (int u = 0; u < 4; u++){
                const float* cw = g_CW + (size_t)(d0 + u)*MMM;
                acc[u] = o0*cw[lane] + o1*cw[lane + 32];
            }
#pragma unroll
            for (int o = 16; o; o >>= 1){
#pragma unroll
                for (int u = 0; u < 4; u++) acc[u] += __shfl_xor_sync(0xffffffffu, acc[u], o);
            }
#pragma unroll
            for (int u = 0; u < 4; u++){
                if (lane == u){
                    int d = d0 + u;
                    st_cg(g_xb + g*DD + d, acc[u] + g_cb[d] + g_E2[((size_t)g*FF + t + 1)*DD + d]);
                }
            }
            group_sync(phase, g);
        }
    } // steps
}

// ---------------- launch ---------------------------------------------------------
extern "C" void kernel_launch(void* const* d_in, const int* in_sizes, int n_in,
                              void* d_out, int out_size){
    const float* content       = (const float*)d_in[0];
    const float* style_code    = (const float*)d_in[1];
    const float* style_hiddens = (const float*)d_in[2];
    const float* init_state    = (const float*)d_in[3];
    const float* ca_in_w  = (const float*)d_in[4];
    const float* ca_in_b  = (const float*)d_in[5];
    const float* ca_out_w = (const float*)d_in[6];
    const float* ca_out_b = (const float*)d_in[7];
    const float* se_w     = (const float*)d_in[8];
    const float* se_b     = (const float*)d_in[9];
    const float* mm_w     = (const float*)d_in[10];
    const float* mm_b     = (const float*)d_in[11];
    const float* mmr_w    = (const float*)d_in[12];
    const float* mmr_b    = (const float*)d_in[13];
    const float* sa_in_w  = (const float*)d_in[14];
    const float* sa_in_b  = (const float*)d_in[15];
    const float* sa_out_w = (const float*)d_in[16];
    const float* sa_out_b = (const float*)d_in[17];
    const float* xa_in_w  = (const float*)d_in[18];
    const float* xa_in_b  = (const float*)d_in[19];
    const float* xa_out_w = (const float*)d_in[20];
    const float* xa_out_b = (const float*)d_in[21];
    const float* ff1_w    = (const float*)d_in[22];
    const float* ff1_b    = (const float*)d_in[23];
    const float* ff2_w    = (const float*)d_in[24];
    const float* ff2_b    = (const float*)d_in[25];
    const float* ln_g     = (const float*)d_in[26];
    const float* ln_b     = (const float*)d_in[27];

    float* dec_out = (float*)d_out;                      // (B,48,64)
    float* sel     = (float*)d_out + BB*FF*MMM;          // (B,48,512)

    float *A_qh, *A_kh, *A_vh, *A_tmpL, *A_XA;
    cudaGetSymbolAddress((void**)&A_qh,   g_qh);
    cudaGetSymbolAddress((void**)&A_kh,   g_kh);
    cudaGetSymbolAddress((void**)&A_vh,   g_vh);
    cudaGetSymbolAddress((void**)&A_tmpL, g_tmpL);
    cudaGetSymbolAddress((void**)&A_XA,   g_XA);

    dim3 blk(256);

    // ---- sel = CA(content, style_hiddens) (nh=1) ----
    ca_inproj_kernel<<<dim3(64, 64, 3), blk>>>(content, style_hiddens, ca_in_w, ca_in_b,
                                               A_qh, A_kh, A_vh);
    ca_attn_kernel<<<BB*FF, 256>>>(A_qh, A_kh, A_vh, A_tmpL);
    gemm_rows_kernel<<<dim3(64, 48), blk>>>(sel, A_tmpL, ca_out_w, ca_out_b, DD, DD);

    // ---- XA[l] = (content @ Wv_l^T + bv_l) @ Wo_l^T + bo_l ----
    gemm_rows_z_kernel<<<dim3(64, 48, LLAY), blk>>>(
        A_tmpL, content, xa_in_w + 2*DD*DD, xa_in_b + 2*DD,
        DD, DD, BB*FF,
        (size_t)BB*FF*DD, 0, (size_t)3*DD*DD, (size_t)3*DD);
    gemm_rows_z_kernel<<<dim3(64, 48, LLAY), blk>>>(
        A_XA, A_tmpL, xa_out_w, xa_out_b,
        DD, DD, BB*FF,
        (size_t)BB*FF*DD, (size_t)BB*FF*DD, (size_t)DD*DD, (size_t)DD);

    // ---- E2 table, folded head weights, x0, barrier reset ----
    e2_kernel<<<dim3(64, 48), 256>>>(sel, se_w, se_b, style_code);
    cw_kernel<<<DD, MMM>>>(se_w, mm_w, mm_b);
    init_x0_kernel<<<BB, 512>>>(init_state, mm_w, mm_b, se_w);
    reset_barrier_kernel<<<1, 32>>>();

    // ---- persistent autoregressive decode (8 independent batch groups) ----
    decode_kernel<<<GRID, 256>>>(sa_in_w, sa_in_b, sa_out_w, sa_out_b,
                                 ff1_w, ff1_b, ff2_w, ff2_b,
                                 ln_g, ln_b, mmr_w, mmr_b, dec_out);
}